// round 17
// baseline (speedup 1.0000x reference)
#include <cuda_runtime.h>
#include <math.h>

#define S_LEN 512
#define B_SZ  64
#define HID   512
#define G3    1536
#define EMB_D 256
#define M_ROWS (S_LEN * B_SZ)   // 32768

typedef unsigned long long ull;
typedef unsigned int uint32;

// ---------------- packed f32x2 helpers (GRU) ---------------------------------
__device__ __forceinline__ ull pk2(float lo, float hi) {
    ull r; asm("mov.b64 %0, {%1,%2};" : "=l"(r) : "f"(lo), "f"(hi)); return r;
}
__device__ __forceinline__ ull dup2(float v) { return pk2(v, v); }
__device__ __forceinline__ void ffma2(ull& d, ull a, ull b) {
    asm("fma.rn.f32x2 %0, %1, %2, %0;" : "+l"(d) : "l"(a), "l"(b));
}
__device__ __forceinline__ ull add2(ull a, ull b) {
    ull r; asm("add.rn.f32x2 %0, %1, %2;" : "=l"(r) : "l"(a), "l"(b)); return r;
}
__device__ __forceinline__ float2 unpk2(ull v) {
    float2 f; asm("mov.b64 {%0,%1}, %2;" : "=f"(f.x), "=f"(f.y) : "l"(v)); return f;
}

// ---------------- tf32 helpers ------------------------------------------------
__device__ __forceinline__ float tf32_rna(float x) {
    uint32 u; asm("cvt.rna.tf32.f32 %0, %1;" : "=r"(u) : "f"(x));
    return __uint_as_float(u);
}
__device__ __forceinline__ void mma_tf32(float* c, const uint32* a,
                                         uint32 b0, uint32 b1) {
    asm volatile(
        "mma.sync.aligned.m16n8k8.row.col.f32.tf32.tf32.f32 "
        "{%0,%1,%2,%3}, {%4,%5,%6,%7}, {%8,%9}, {%0,%1,%2,%3};"
        : "+f"(c[0]), "+f"(c[1]), "+f"(c[2]), "+f"(c[3])
        : "r"(a[0]), "r"(a[1]), "r"(a[2]), "r"(a[3]), "r"(b0), "r"(b1));
}

// ---------------- scratch (static device globals; no allocation) ------------
__device__ float g_xemb[(size_t)M_ROWS * EMB_D];   // 32 MB
__device__ float g_w0hi[G3 * EMB_D], g_w0lo[G3 * EMB_D];
__device__ float g_w1hi[G3 * HID],  g_w1lo[G3 * HID];
__device__ float g_xg[(size_t)M_ROWS * G3];        // 192 MB
__device__ float g_ys[(size_t)M_ROWS * HID];       // 64 MB
__device__ unsigned int g_flags[4][32][32];         // one flag per 128B line

// ---------------- tf32 split for weights (elementwise, float4) ---------------
__global__ void split_kernel(const float* __restrict__ src,
                             float* __restrict__ hi, float* __restrict__ lo,
                             int n4) {
    int i = blockIdx.x * blockDim.x + threadIdx.x;
    if (i >= n4) return;
    float4 v = ((const float4*)src)[i];
    float4 h, l;
    h.x = tf32_rna(v.x); l.x = tf32_rna(v.x - h.x);
    h.y = tf32_rna(v.y); l.y = tf32_rna(v.y - h.y);
    h.z = tf32_rna(v.z); l.z = tf32_rna(v.z - h.z);
    h.w = tf32_rna(v.w); l.w = tf32_rna(v.w - h.w);
    ((float4*)hi)[i] = h;
    ((float4*)lo)[i] = l;
}

// ---------------- embedding gather ------------------------------------------
__global__ void embed_kernel(const int* __restrict__ x,
                             const float* __restrict__ emb,
                             float* __restrict__ out) {
    int w    = (blockIdx.x << 3) + (threadIdx.x >> 5);
    int lane = threadIdx.x & 31;
    int s = w >> 6, b = w & 63;
    int tok = x[b * S_LEN + s];
    float4* dst = (float4*)(out + (size_t)w * EMB_D);
    if (tok == 0) {
        float4 z = make_float4(0.f, 0.f, 0.f, 0.f);
        dst[lane] = z; dst[lane + 32] = z;
    } else {
        const float4* src = (const float4*)(emb + (size_t)tok * EMB_D);
        dst[lane] = src[lane]; dst[lane + 32] = src[lane + 32];
    }
}

// ---------------- tensor-core GEMM: C = A @ W^T + bias (3xTF32) --------------
// A is fp32 (split into tf32 hi/lo during staging). W pre-split (hi/lo).
// Block 128m x 128n, 8 warps (32m x 64n each), K-chunk 16, register prefetch.
#define TCS 20
__global__ void __launch_bounds__(256, 2) gemm_tc_kernel(
    const float* __restrict__ A,
    const float* __restrict__ Whi, const float* __restrict__ Wlo,
    const float* __restrict__ bias, float* __restrict__ C,
    int M, int N, int K)
{
    __shared__ float sAh[128 * TCS], sAl[128 * TCS];
    __shared__ float sBh[128 * TCS], sBl[128 * TCS];

    const int tid  = threadIdx.x;
    const int n0   = blockIdx.x * 128;
    const int m0   = blockIdx.y * 128;
    const int w    = tid >> 5, lane = tid & 31;
    const int mw   = (w & 3) * 32, nw = (w >> 2) * 64;
    const int g    = lane >> 2, tig = lane & 3;

    float acc[2][8][4];
#pragma unroll
    for (int mt = 0; mt < 2; mt++)
#pragma unroll
        for (int nt = 0; nt < 8; nt++)
#pragma unroll
            for (int i = 0; i < 4; i++) acc[mt][nt][i] = 0.f;

    // staging registers (prefetch buffer)
    float4 va[2], vbh[2], vbl[2];

    // preload chunk 0
#pragma unroll
    for (int it = 0; it < 2; it++) {
        int item = tid + it * 256;
        int r = item >> 2, qq = (item & 3) * 4;
        va[it]  = *(const float4*)(A   + (size_t)(m0 + r) * K + qq);
        vbh[it] = *(const float4*)(Whi + (size_t)(n0 + r) * K + qq);
        vbl[it] = *(const float4*)(Wlo + (size_t)(n0 + r) * K + qq);
    }
#pragma unroll
    for (int it = 0; it < 2; it++) {
        int item = tid + it * 256;
        int r = item >> 2, qq = (item & 3) * 4;
        float4 v = va[it], h, l;
        h.x = tf32_rna(v.x); l.x = tf32_rna(v.x - h.x);
        h.y = tf32_rna(v.y); l.y = tf32_rna(v.y - h.y);
        h.z = tf32_rna(v.z); l.z = tf32_rna(v.z - h.z);
        h.w = tf32_rna(v.w); l.w = tf32_rna(v.w - h.w);
        *(float4*)(sAh + r * TCS + qq) = h;
        *(float4*)(sAl + r * TCS + qq) = l;
        *(float4*)(sBh + r * TCS + qq) = vbh[it];
        *(float4*)(sBl + r * TCS + qq) = vbl[it];
    }
    __syncthreads();

    for (int kc = 0; kc < K; kc += 16) {
        const bool pf = (kc + 16) < K;
        if (pf) {
#pragma unroll
            for (int it = 0; it < 2; it++) {
                int item = tid + it * 256;
                int r = item >> 2, qq = (item & 3) * 4;
                va[it]  = *(const float4*)(A   + (size_t)(m0 + r) * K + kc + 16 + qq);
                vbh[it] = *(const float4*)(Whi + (size_t)(n0 + r) * K + kc + 16 + qq);
                vbl[it] = *(const float4*)(Wlo + (size_t)(n0 + r) * K + kc + 16 + qq);
            }
        }

#pragma unroll
        for (int k8 = 0; k8 < 2; k8++) {
            const int kb = k8 * 8;
            uint32 ah[2][4], al[2][4];
#pragma unroll
            for (int mt = 0; mt < 2; mt++) {
                int mbase = mw + mt * 16;
                ah[mt][0] = __float_as_uint(sAh[(mbase + g) * TCS + kb + tig]);
                ah[mt][1] = __float_as_uint(sAh[(mbase + g + 8) * TCS + kb + tig]);
                ah[mt][2] = __float_as_uint(sAh[(mbase + g) * TCS + kb + tig + 4]);
                ah[mt][3] = __float_as_uint(sAh[(mbase + g + 8) * TCS + kb + tig + 4]);
                al[mt][0] = __float_as_uint(sAl[(mbase + g) * TCS + kb + tig]);
                al[mt][1] = __float_as_uint(sAl[(mbase + g + 8) * TCS + kb + tig]);
                al[mt][2] = __float_as_uint(sAl[(mbase + g) * TCS + kb + tig + 4]);
                al[mt][3] = __float_as_uint(sAl[(mbase + g + 8) * TCS + kb + tig + 4]);
            }
#pragma unroll
            for (int nt = 0; nt < 8; nt++) {
                int nb = (nw + nt * 8 + g) * TCS + kb + tig;
                uint32 bh0 = __float_as_uint(sBh[nb]);
                uint32 bh1 = __float_as_uint(sBh[nb + 4]);
                uint32 bl0 = __float_as_uint(sBl[nb]);
                uint32 bl1 = __float_as_uint(sBl[nb + 4]);
#pragma unroll
                for (int mt = 0; mt < 2; mt++) {
                    mma_tf32(acc[mt][nt], ah[mt], bh0, bh1);   // hi*hi
                    mma_tf32(acc[mt][nt], ah[mt], bl0, bl1);   // hi*lo
                    mma_tf32(acc[mt][nt], al[mt], bh0, bh1);   // lo*hi
                }
            }
        }
        __syncthreads();
        if (pf) {
#pragma unroll
            for (int it = 0; it < 2; it++) {
                int item = tid + it * 256;
                int r = item >> 2, qq = (item & 3) * 4;
                float4 v = va[it], h, l;
                h.x = tf32_rna(v.x); l.x = tf32_rna(v.x - h.x);
                h.y = tf32_rna(v.y); l.y = tf32_rna(v.y - h.y);
                h.z = tf32_rna(v.z); l.z = tf32_rna(v.z - h.z);
                h.w = tf32_rna(v.w); l.w = tf32_rna(v.w - h.w);
                *(float4*)(sAh + r * TCS + qq) = h;
                *(float4*)(sAl + r * TCS + qq) = l;
                *(float4*)(sBh + r * TCS + qq) = vbh[it];
                *(float4*)(sBl + r * TCS + qq) = vbl[it];
            }
            __syncthreads();
        }
    }

    // epilogue: c0,c1 -> (m, n..n+1), c2,c3 -> (m+8, n..n+1)
#pragma unroll
    for (int mt = 0; mt < 2; mt++) {
#pragma unroll
        for (int nt = 0; nt < 8; nt++) {
            int n = n0 + nw + nt * 8 + 2 * tig;
            float2 bb = *(const float2*)&bias[n];
            int m = m0 + mw + mt * 16 + g;
            float2 v0 = make_float2(acc[mt][nt][0] + bb.x, acc[mt][nt][1] + bb.y);
            float2 v1 = make_float2(acc[mt][nt][2] + bb.x, acc[mt][nt][3] + bb.y);
            *(float2*)(C + (size_t)m * N + n)       = v0;
            *(float2*)(C + (size_t)(m + 8) * N + n) = v1;
        }
    }
}

// ---------------- GRU recurrence (R13 exact) ----------------------------------
#define HS 20
#define P4STRIDE 17
#define GRU_SMEM_FLOATS (512 * HS + 16 * 16 * P4STRIDE * 4)
#define GRU_SMEM_BYTES  (GRU_SMEM_FLOATS * 4)

__device__ __forceinline__ unsigned ld_acq(const unsigned* p) {
    unsigned v;
    asm volatile("ld.global.acquire.gpu.u32 %0, [%1];" : "=r"(v) : "l"(p) : "memory");
    return v;
}
__device__ __forceinline__ void st_rel(unsigned* p, unsigned v) {
    asm volatile("st.global.release.gpu.u32 [%0], %1;" :: "l"(p), "r"(v) : "memory");
}

__global__ void __launch_bounds__(512, 1) gru_kernel(
    const float* __restrict__ xg,    // [S][64][1536]
    const float* __restrict__ Whh,   // [1536][512]
    const float* __restrict__ bhh,   // [1536]
    float* __restrict__ ys)          // [S][64][512]
{
    extern __shared__ float sm[];
    float* hsh  = sm;                          // 512*20
    float* part = hsh + 512 * HS;              // 16*16*17*4
    __shared__ unsigned sh_base;

    const int tid = threadIdx.x;
    const int bg  = blockIdx.x & 3;
    const int dg  = blockIdx.x >> 2;
    const int rowBase = bg * 16;
    const int dimBase = dg * 16;

    if (tid == 0) sh_base = *(volatile unsigned*)&g_flags[bg][dg][0];

    // gating role (tid < 256): one thread per (row, dim); h_old in a register
    const int myrow = (tid >> 4) & 15;
    const int mydl  = tid & 15;
    const int mydim = dimBase + mydl;
    float b_r = 0.f, b_z = 0.f, b_n = 0.f;
    float h_old = 0.f;
    if (tid < 256) {
        b_r = bhh[mydim]; b_z = bhh[512 + mydim]; b_n = bhh[1024 + mydim];
    }

    // compute role
    const int w    = tid >> 5;            // warp 0..15, k chunk [32w, 32w+32)
    const int lane = tid & 31;
    const int half = lane >> 4;           // 0: even k, 1: odd k
    const int l    = lane & 15;           // owned dim (local)
    const int k0   = w * 32;

    // W_hh slice -> registers
    float wreg[48];
#pragma unroll
    for (int it = 0; it < 16; ++it) {
        const int k = k0 + 2 * it + half;
#pragma unroll
        for (int g = 0; g < 3; g++)
            wreg[it * 3 + g] = Whh[(size_t)(g * 512 + dimBase + l) * 512 + k];
    }

    __syncthreads();
    const unsigned base = sh_base;

    for (int t = 0; t < S_LEN; ++t) {
        float xr = 0.f, xz = 0.f, xn = 0.f;
        if (tid < 256) {
            size_t xbase = ((size_t)t * 64 + rowBase + myrow) * G3 + mydim;
            xr = xg[xbase]; xz = xg[xbase + 512]; xn = xg[xbase + 1024];
        }

        if (t == 0) {
            for (int idx = lane; idx < 32 * HS; idx += 32)
                hsh[k0 * HS + idx] = 0.f;
            __syncwarp();
        } else {
            const unsigned target = base + (unsigned)t;
            const float4* hsrc4 = (const float4*)(ys + ((size_t)(t - 1) * 64 + rowBase) * HID);
            float4 v[2][2];
#pragma unroll
            for (int j = 0; j < 2; j++) {
                const int c = 2 * w + j;
                const unsigned* fp = &g_flags[bg][c][0];
                while ((int)(ld_acq(fp) - target) < 0) { }
#pragma unroll
                for (int i = 0; i < 2; i++) {
                    int idx = i * 32 + lane;
                    int r = idx & 15, fq = idx >> 4;
                    v[j][i] = __ldcg(hsrc4 + (size_t)r * 128 + c * 4 + fq);
                }
            }
#pragma unroll
            for (int j = 0; j < 2; j++) {
                const int c = 2 * w + j;
#pragma unroll
                for (int i = 0; i < 2; i++) {
                    int idx = i * 32 + lane;
                    int r = idx & 15, fq = idx >> 4;
                    int kb = c * 16 + fq * 4;
                    hsh[(kb + 0) * HS + r] = v[j][i].x;
                    hsh[(kb + 1) * HS + r] = v[j][i].y;
                    hsh[(kb + 2) * HS + r] = v[j][i].z;
                    hsh[(kb + 3) * HS + r] = v[j][i].w;
                }
            }
            __syncwarp();
        }

        ull acc[24];
#pragma unroll
        for (int i = 0; i < 24; i++) acc[i] = 0ULL;
#pragma unroll 4
        for (int it = 0; it < 16; ++it) {
            const int k = k0 + 2 * it + half;
            ull wr2 = dup2(wreg[it * 3 + 0]);
            ull wz2 = dup2(wreg[it * 3 + 1]);
            ull wn2 = dup2(wreg[it * 3 + 2]);
            const float* hk = hsh + k * HS;
            ulonglong2 hq[4];
#pragma unroll
            for (int q = 0; q < 4; q++) hq[q] = *(const ulonglong2*)(hk + 4 * q);
            ull hp[8] = { hq[0].x, hq[0].y, hq[1].x, hq[1].y,
                          hq[2].x, hq[2].y, hq[3].x, hq[3].y };
#pragma unroll
            for (int j = 0; j < 8; j++) {
                ffma2(acc[j * 3 + 0], hp[j], wr2);
                ffma2(acc[j * 3 + 1], hp[j], wz2);
                ffma2(acc[j * 3 + 2], hp[j], wn2);
            }
        }

#pragma unroll
        for (int i = 0; i < 24; i++) {
            ull o = __shfl_down_sync(0xffffffffu, acc[i], 16);
            acc[i] = add2(acc[i], o);
        }

        if (half == 0) {
#pragma unroll
            for (int j = 0; j < 8; j++) {
                float2 r2 = unpk2(acc[j * 3 + 0]);
                float2 z2 = unpk2(acc[j * 3 + 1]);
                float2 n2 = unpk2(acc[j * 3 + 2]);
                float* pp0 = part + (((w * 16 + 2 * j) * P4STRIDE + l) << 2);
                float* pp1 = part + (((w * 16 + 2 * j + 1) * P4STRIDE + l) << 2);
                *(float4*)pp0 = make_float4(r2.x, z2.x, n2.x, 0.f);
                *(float4*)pp1 = make_float4(r2.y, z2.y, n2.y, 0.f);
            }
        }
        __syncthreads();

        if (tid < 256) {
            float hr = b_r, hz = b_z, hn = b_n;
#pragma unroll
            for (int kk = 0; kk < 16; kk++) {
                float4 p = *(const float4*)(part +
                    (((kk * 16 + myrow) * P4STRIDE + mydl) << 2));
                hr += p.x; hz += p.y; hn += p.z;
            }
            float er = __expf(-(xr + hr));
            float rr = __fdividef(1.f, 1.f + er);
            float ez = __expf(-(xz + hz));
            float zz = __fdividef(1.f, 1.f + ez);
            float an = xn + rr * hn;
            float e2 = __expf(2.f * an);
            float nn = 1.f - __fdividef(2.f, e2 + 1.f);   // tanh(an)
            float hnew = (1.f - zz) * nn + zz * h_old;
            h_old = hnew;
            ys[((size_t)t * 64 + rowBase + myrow) * HID + mydim] = hnew;
        }

        __syncthreads();
        if (tid == 0) st_rel(&g_flags[bg][dg][0], base + (unsigned)t + 1u);
    }
}

// ---------------- final FC + sigmoid ----------------------------------------
__global__ void fc_kernel(const float* __restrict__ ys,
                          const float* __restrict__ Wfc,
                          const float* __restrict__ bfc,
                          float* __restrict__ out) {
    int b = blockIdx.x, tid = threadIdx.x;
    const float* h = ys + ((size_t)(S_LEN - 1) * 64 + b) * HID;
    float s = 0.f;
    for (int i = tid; i < HID; i += 128) s += h[i] * Wfc[i];
#pragma unroll
    for (int o = 16; o; o >>= 1) s += __shfl_down_sync(0xffffffffu, s, o);
    __shared__ float ps[4];
    if ((tid & 31) == 0) ps[tid >> 5] = s;
    __syncthreads();
    if (tid == 0) {
        float v = ps[0] + ps[1] + ps[2] + ps[3] + bfc[0];
        out[b] = 1.f / (1.f + expf(-v));
    }
}

// ---------------- launch ----------------------------------------------------
extern "C" void kernel_launch(void* const* d_in, const int* in_sizes, int n_in,
                              void* d_out, int out_size) {
    (void)in_sizes; (void)n_in; (void)out_size;
    const int*   x    = (const int*)  d_in[0];
    const float* emb  = (const float*)d_in[1];
    const float* Wih0 = (const float*)d_in[2];
    const float* Whh0 = (const float*)d_in[3];
    const float* bih0 = (const float*)d_in[4];
    const float* bhh0 = (const float*)d_in[5];
    const float* Wih1 = (const float*)d_in[6];
    const float* Whh1 = (const float*)d_in[7];
    const float* bih1 = (const float*)d_in[8];
    const float* bhh1 = (const float*)d_in[9];
    const float* Wfc  = (const float*)d_in[10];
    const float* bfc  = (const float*)d_in[11];
    float* out = (float*)d_out;

    float *xemb, *w0hi, *w0lo, *w1hi, *w1lo, *xgbuf, *ysbuf;
    cudaGetSymbolAddress((void**)&xemb, g_xemb);
    cudaGetSymbolAddress((void**)&w0hi, g_w0hi);
    cudaGetSymbolAddress((void**)&w0lo, g_w0lo);
    cudaGetSymbolAddress((void**)&w1hi, g_w1hi);
    cudaGetSymbolAddress((void**)&w1lo, g_w1lo);
    cudaGetSymbolAddress((void**)&xgbuf, g_xg);
    cudaGetSymbolAddress((void**)&ysbuf, g_ys);

    cudaFuncSetAttribute(gru_kernel, cudaFuncAttributeMaxDynamicSharedMemorySize,
                         GRU_SMEM_BYTES);

    // weight splits (small)
    split_kernel<<<(G3 * EMB_D / 4 + 255) / 256, 256>>>(Wih0, w0hi, w0lo, G3 * EMB_D / 4);
    split_kernel<<<(G3 * HID / 4 + 255) / 256, 256>>>(Wih1, w1hi, w1lo, G3 * HID / 4);

    embed_kernel<<<4096, 256>>>(x, emb, xemb);

    gemm_tc_kernel<<<dim3(G3 / 128, M_ROWS / 128), 256>>>(
        xemb, w0hi, w0lo, bih0, xgbuf, M_ROWS, G3, EMB_D);
    gru_kernel<<<128, 512, GRU_SMEM_BYTES>>>(xgbuf, Whh0, bhh0, ysbuf);

    gemm_tc_kernel<<<dim3(G3 / 128, M_ROWS / 128), 256>>>(
        ysbuf, w1hi, w1lo, bih1, xgbuf, M_ROWS, G3, HID);
    gru_kernel<<<128, 512, GRU_SMEM_BYTES>>>(xgbuf, Whh1, bhh1, ysbuf);

    fc_kernel<<<64, 128>>>(ysbuf, Wfc, bfc, out);
}